// round 3
// baseline (speedup 1.0000x reference)
#include <cuda_runtime.h>

#define NN 50000
#define NE 3200000
#define FULL 0xFFFFFFFFu

// ---------------- scratch (static device buffers; no allocs) ----------------
__device__ int    g_is64;
__device__ int    g_cnt[NN];
__device__ int    g_cur[NN];
__device__ int    g_row[NN + 1];
__device__ int    g_psrc[NE];
__device__ float  g_pea[NE * 5];        // permuted edge_attr (grouped by dst)
__device__ float2 g_np2[NN * 32];       // node_proj, col-pair layout (l, l+32)
__device__ float2 g_ag2[NN * 32];       // aggr,      col-pair layout (l, l+32)
__device__ float  g_xb[2 * NN * 8];     // ping-pong node features

// ---------------- dtype detection for edge_index ----------------
// int64 values < 50000 -> every odd 32-bit word is 0. int32 -> odd words are
// random node ids. Sample 65536 odd words (well within either buffer size).
__global__ void k_detect(const unsigned int* __restrict__ ei32) {
    __shared__ int nz;
    if (threadIdx.x == 0) nz = 0;
    __syncthreads();
    int local = 0;
    for (int i = threadIdx.x; i < 65536; i += 256)
        if (ei32[2 * i + 1] != 0u) local = 1;
    if (local) atomicExch(&nz, 1);
    __syncthreads();
    if (threadIdx.x == 0) g_is64 = nz ? 0 : 1;
}

__device__ __forceinline__ int load_idx(const void* eiv, long long i) {
    if (g_is64) return (int)((const long long*)eiv)[i];
    return ((const int*)eiv)[i];
}

// ---------------- counting sort of edges by dst ----------------
__global__ void k_zero() {
    int t = blockIdx.x * blockDim.x + threadIdx.x;
    if (t < NN) g_cnt[t] = 0;
}

__global__ void k_hist(const void* __restrict__ eiv) {
    int e = blockIdx.x * blockDim.x + threadIdx.x;
    if (e < NE) {
        int dst = load_idx(eiv, (long long)NE + e);
        if ((unsigned)dst < NN) atomicAdd(&g_cnt[dst], 1);
    }
}

__global__ void k_scan() {
    __shared__ int sh[1024];
    __shared__ int carry;
    int t = threadIdx.x;
    if (t == 0) carry = 0;
    __syncthreads();
    for (int base = 0; base < NN; base += 1024) {
        int i = base + t;
        int v = (i < NN) ? g_cnt[i] : 0;
        sh[t] = v;
        __syncthreads();
        for (int off = 1; off < 1024; off <<= 1) {
            int a = (t >= off) ? sh[t - off] : 0;
            __syncthreads();
            sh[t] += a;
            __syncthreads();
        }
        if (i < NN) {
            int ex = sh[t] - v + carry;
            g_row[i] = ex;
            g_cur[i] = ex;
        }
        __syncthreads();
        if (t == 0) carry += sh[1023];
        __syncthreads();
    }
    if (t == 0) g_row[NN] = carry;
}

__global__ void k_scatter(const void* __restrict__ eiv,
                          const float* __restrict__ ea) {
    int e = blockIdx.x * blockDim.x + threadIdx.x;
    if (e >= NE) return;
    int src = load_idx(eiv, e);
    int dst = load_idx(eiv, (long long)NE + e);
    if ((unsigned)dst >= NN) return;
    if ((unsigned)src >= NN) src = 0;
    int pos = atomicAdd(&g_cur[dst], 1);
    g_psrc[pos] = src;
#pragma unroll
    for (int i = 0; i < 5; i++) g_pea[pos * 5 + i] = ea[e * 5 + i];
}

// ---------------- per-iteration: node projection (x @ w1_0[:8] + b1_0) ----------------
__global__ void k_np(const float* __restrict__ x_ext, int it,
                     const float* __restrict__ w10,
                     const float* __restrict__ b10) {
    const float* x = (it == 0) ? x_ext : g_xb + ((it + 1) & 1) * NN * 8;
    int t = blockIdx.x * blockDim.x + threadIdx.x;
    if (t >= NN * 32) return;
    int n = t >> 5, l = t & 31;
    float v0 = b10[l], v1 = b10[l + 32];
#pragma unroll
    for (int i = 0; i < 8; i++) {
        float xv = x[n * 8 + i];
        v0 = fmaf(xv, w10[i * 64 + l], v0);
        v1 = fmaf(xv, w10[i * 64 + l + 32], v1);
    }
    g_np2[t] = make_float2(v0, v1);
}

// ---------------- per-iteration: fused edge MLP + segment max ----------------
// One warp per dst node; processes its contiguous (sorted) edge segment,
// 4 edges at a time (remainder padded by repeating last edge: max-idempotent).
__global__ void __launch_bounds__(256) k_edge(const float* __restrict__ w10,
                                              const float* __restrict__ w11,
                                              const float* __restrict__ b11) {
    __shared__ float2 shw[64 * 32];  // w1_1 as (col l, col l+32) pairs per row k
    int tid = threadIdx.x;
    for (int i = tid; i < 64 * 32; i += 256) {
        int k = i >> 5, l = i & 31;
        shw[i] = make_float2(w11[k * 64 + l], w11[k * 64 + l + 32]);
    }
    int lane = tid & 31, w = tid >> 5;
    float2 w10r[5];
#pragma unroll
    for (int i = 0; i < 5; i++)
        w10r[i] = make_float2(w10[(8 + i) * 64 + lane], w10[(8 + i) * 64 + 32 + lane]);
    float2 bb = make_float2(b11[lane], b11[lane + 32]);
    __syncthreads();

    int n = blockIdx.x * 8 + w;
    int s = g_row[n], e = g_row[n + 1];
    float a0 = 0.f, a1 = 0.f;

    for (int eb = s; eb < e; eb += 4) {
        int idx[4];
#pragma unroll
        for (int j = 0; j < 4; j++) idx[j] = min(eb + j, e - 1);

        float hl[4], hh[4], eav[4];
#pragma unroll
        for (int j = 0; j < 4; j++) {
            int src = g_psrc[idx[j]];
            float2 np = g_np2[src * 32 + lane];
            hl[j] = np.x;
            hh[j] = np.y;
            eav[j] = (lane < 5) ? g_pea[idx[j] * 5 + lane] : 0.f;
        }
        // layer-1 edge_attr contribution
#pragma unroll
        for (int i = 0; i < 5; i++) {
#pragma unroll
            for (int j = 0; j < 4; j++) {
                float sv = __shfl_sync(FULL, eav[j], i);
                hl[j] = fmaf(sv, w10r[i].x, hl[j]);
                hh[j] = fmaf(sv, w10r[i].y, hh[j]);
            }
        }
        float m0[4], m1[4];
#pragma unroll
        for (int j = 0; j < 4; j++) {
            hl[j] = fmaxf(hl[j], 0.f);
            hh[j] = fmaxf(hh[j], 0.f);
            m0[j] = bb.x;
            m1[j] = bb.y;
        }
        // layer-2: msg = relu(h @ w1_1 + b1_1)
#pragma unroll
        for (int k = 0; k < 32; k++) {
            float2 wv = shw[k * 32 + lane];
#pragma unroll
            for (int j = 0; j < 4; j++) {
                float hk = __shfl_sync(FULL, hl[j], k);
                m0[j] = fmaf(hk, wv.x, m0[j]);
                m1[j] = fmaf(hk, wv.y, m1[j]);
            }
        }
#pragma unroll
        for (int k = 0; k < 32; k++) {
            float2 wv = shw[(k + 32) * 32 + lane];
#pragma unroll
            for (int j = 0; j < 4; j++) {
                float hk = __shfl_sync(FULL, hh[j], k);
                m0[j] = fmaf(hk, wv.x, m0[j]);
                m1[j] = fmaf(hk, wv.y, m1[j]);
            }
        }
#pragma unroll
        for (int j = 0; j < 4; j++) {
            a0 = fmaxf(a0, fmaxf(m0[j], 0.f));
            a1 = fmaxf(a1, fmaxf(m1[j], 0.f));
        }
    }
    g_ag2[n * 32 + lane] = make_float2(a0, a1);
}

// ---------------- per-iteration: node MLP + normalize + output assembly ----------------
__global__ void __launch_bounds__(256) k_node(const float* __restrict__ x_ext,
                                              float* __restrict__ out_ext, int it,
                                              const float* __restrict__ w20,
                                              const float* __restrict__ b20,
                                              const float* __restrict__ w21,
                                              const float* __restrict__ b21) {
    const float* xin = (it == 0) ? x_ext : g_xb + ((it + 1) & 1) * NN * 8;
    float* xout = (it == 7) ? out_ext : g_xb + (it & 1) * NN * 8;

    __shared__ float shw[72 * 32];
    int tid = threadIdx.x;
    for (int i = tid; i < 72 * 32; i += 256) shw[i] = w20[i];
    int lane = tid & 31, w = tid >> 5;
    float w21r[5];
#pragma unroll
    for (int j = 0; j < 5; j++) w21r[j] = w21[lane * 5 + j];
    __syncthreads();

    int n = blockIdx.x * 8 + w;
    float2 a2 = g_ag2[n * 32 + lane];
    float xv = (lane < 8) ? xin[n * 8 + lane] : 0.f;
    float acc = b20[lane];
#pragma unroll
    for (int i = 0; i < 8; i++) {
        float s = __shfl_sync(FULL, xv, i);
        acc = fmaf(s, shw[i * 32 + lane], acc);
    }
#pragma unroll
    for (int i = 0; i < 32; i++) {
        float s = __shfl_sync(FULL, a2.x, i);
        acc = fmaf(s, shw[(8 + i) * 32 + lane], acc);
    }
#pragma unroll
    for (int i = 0; i < 32; i++) {
        float s = __shfl_sync(FULL, a2.y, i);
        acc = fmaf(s, shw[(40 + i) * 32 + lane], acc);
    }
    acc = fmaxf(acc, 0.f);

    float p0 = acc * w21r[0], p1 = acc * w21r[1], p2 = acc * w21r[2],
          p3 = acc * w21r[3], p4 = acc * w21r[4];
#pragma unroll
    for (int off = 16; off > 0; off >>= 1) {
        p0 += __shfl_xor_sync(FULL, p0, off);
        p1 += __shfl_xor_sync(FULL, p1, off);
        p2 += __shfl_xor_sync(FULL, p2, off);
        p3 += __shfl_xor_sync(FULL, p3, off);
        p4 += __shfl_xor_sync(FULL, p4, off);
    }
    float links = p0 + b21[0];
    float c0 = p1 + b21[1], c1 = p2 + b21[2], c2 = p3 + b21[3], c3 = p4 + b21[4];
    float nor = sqrtf(c0 * c0 + c1 * c1 + c2 * c2 + c3 * c3);
    float scale = 1.f / fmaxf(1.f, nor);

    float outv = 0.f;
    if (lane == 0)      outv = links;
    else if (lane == 1) outv = c0 * scale;
    else if (lane == 2) outv = c1 * scale;
    else if (lane == 3) outv = c2 * scale;
    else if (lane == 4) outv = c3 * scale;
    else if (lane < 8)  outv = xin[n * 8 + (lane - 5)];
    if (lane < 8) xout[n * 8 + lane] = outv;
}

// ---------------- launch ----------------
extern "C" void kernel_launch(void* const* d_in, const int* in_sizes, int n_in,
                              void* d_out, int out_size) {
    // Map inputs by size: handles BOTH element counts and byte counts (the
    // two value sets are disjoint). b1_0/b1_1 collide; resolved by order.
    const float* x = 0; const float* ea = 0; const void* ei = 0;
    const float* w10 = 0; const float* b10 = 0; const float* w11 = 0; const float* b11 = 0;
    const float* w20 = 0; const float* b20 = 0; const float* w21 = 0; const float* b21 = 0;
    for (int i = 0; i < n_in; i++) {
        int sz = in_sizes[i];
        const void* p = d_in[i];
        switch (sz) {
            // element counts
            case 400000:   x   = (const float*)p; break;
            case 16000000: ea  = (const float*)p; break;
            case 6400000:  ei  = p; break;
            case 832:      w10 = (const float*)p; break;
            case 64:       if (!b10) b10 = (const float*)p; else b11 = (const float*)p; break;
            case 4096:     w11 = (const float*)p; break;
            case 2304:     w20 = (const float*)p; break;
            case 32:       b20 = (const float*)p; break;
            case 160:      w21 = (const float*)p; break;
            case 5:        b21 = (const float*)p; break;
            // byte counts (fallback interpretation)
            case 1600000:  x   = (const float*)p; break;
            case 64000000: ea  = (const float*)p; break;
            case 51200000: ei  = p; break;   // int64 bytes
            case 25600000: ei  = p; break;   // int32 bytes
            case 3328:     w10 = (const float*)p; break;
            case 256:      if (!b10) b10 = (const float*)p; else b11 = (const float*)p; break;
            case 16384:    w11 = (const float*)p; break;
            case 9216:     w20 = (const float*)p; break;
            case 128:      b20 = (const float*)p; break;
            case 640:      w21 = (const float*)p; break;
            case 20:       b21 = (const float*)p; break;
            default: break;
        }
    }
    // Positional fallback (declaration order of setup_inputs) if anything missed.
    if (!x || !ea || !ei || !w10 || !b10 || !w11 || !b11 || !w20 || !b20 || !w21 || !b21) {
        if (n_in >= 11) {
            x   = (const float*)d_in[0];
            ea  = (const float*)d_in[1];
            ei  = d_in[2];
            w10 = (const float*)d_in[3];
            b10 = (const float*)d_in[4];
            w11 = (const float*)d_in[5];
            b11 = (const float*)d_in[6];
            w20 = (const float*)d_in[7];
            b20 = (const float*)d_in[8];
            w21 = (const float*)d_in[9];
            b21 = (const float*)d_in[10];
        }
    }
    float* out = (float*)d_out;

    // one-time (per launch) edge grouping by dst
    k_detect<<<1, 256>>>((const unsigned int*)ei);
    k_zero<<<(NN + 255) / 256, 256>>>();
    k_hist<<<(NE + 255) / 256, 256>>>(ei);
    k_scan<<<1, 1024>>>();
    k_scatter<<<(NE + 255) / 256, 256>>>(ei, ea);

    for (int it = 0; it < 8; it++) {
        k_np<<<(NN * 32 + 255) / 256, 256>>>(x, it, w10, b10);
        k_edge<<<NN / 8, 256>>>(w10, w11, b11);
        k_node<<<NN / 8, 256>>>(x, out, it, w20, b20, w21, b21);
    }
}

// round 4
// speedup vs baseline: 1.0292x; 1.0292x over previous
#include <cuda_runtime.h>

#define NN 50000
#define NE 3200000
#define FULL 0xFFFFFFFFu

// ---------------- scratch (static device buffers; no allocs) ----------------
__device__ int    g_is64;
__device__ int    g_wctr[8];            // per-iteration work counters (k_edge)
__device__ int    g_cnt[NN];
__device__ int    g_cur[NN];
__device__ int    g_row[NN + 1];
__device__ int    g_psrc[NE];
__device__ float  g_pea[NE * 5];        // permuted edge_attr (grouped by dst)
__device__ float2 g_np2[NN * 32];       // node_proj, col-pair layout (l, l+32)
__device__ float2 g_ag2[NN * 32];       // aggr,      col-pair layout (l, l+32)
__device__ float  g_xb[2 * NN * 8];     // ping-pong node features

// ---------------- dtype detection for edge_index ----------------
__global__ void k_detect(const unsigned int* __restrict__ ei32) {
    __shared__ int nz;
    if (threadIdx.x == 0) nz = 0;
    __syncthreads();
    int local = 0;
    for (int i = threadIdx.x; i < 65536; i += 256)
        if (ei32[2 * i + 1] != 0u) local = 1;
    if (local) atomicExch(&nz, 1);
    __syncthreads();
    if (threadIdx.x == 0) g_is64 = nz ? 0 : 1;
}

__device__ __forceinline__ int load_idx(const void* eiv, long long i) {
    if (g_is64) return (int)((const long long*)eiv)[i];
    return ((const int*)eiv)[i];
}

// ---------------- counting sort of edges by dst ----------------
__global__ void k_zero() {
    int t = blockIdx.x * blockDim.x + threadIdx.x;
    if (t < NN) g_cnt[t] = 0;
    if (t < 8) g_wctr[t] = 0;
}

__global__ void k_hist(const void* __restrict__ eiv) {
    int e = blockIdx.x * blockDim.x + threadIdx.x;
    if (e < NE) {
        int dst = load_idx(eiv, (long long)NE + e);
        if ((unsigned)dst < NN) atomicAdd(&g_cnt[dst], 1);
    }
}

// shfl-based single-block scan (exclusive) over g_cnt -> g_row/g_cur
__global__ void k_scan() {
    __shared__ int wsum[32];
    __shared__ int carry;
    int t = threadIdx.x, lane = t & 31, wid = t >> 5;
    if (t == 0) carry = 0;
    __syncthreads();
    for (int base = 0; base < NN; base += 1024) {
        int i = base + t;
        int v = (i < NN) ? g_cnt[i] : 0;
        int s = v;
#pragma unroll
        for (int off = 1; off < 32; off <<= 1) {
            int tmp = __shfl_up_sync(FULL, s, off);
            if (lane >= off) s += tmp;
        }
        if (lane == 31) wsum[wid] = s;
        __syncthreads();
        if (wid == 0) {
            int ws = wsum[lane];
#pragma unroll
            for (int off = 1; off < 32; off <<= 1) {
                int tmp = __shfl_up_sync(FULL, ws, off);
                if (lane >= off) ws += tmp;
            }
            wsum[lane] = ws;
        }
        __syncthreads();
        int blockoff = ((wid > 0) ? wsum[wid - 1] : 0) + carry;
        int ex = blockoff + s - v;
        if (i < NN) { g_row[i] = ex; g_cur[i] = ex; }
        __syncthreads();
        if (t == 0) carry += wsum[31];
        __syncthreads();
    }
    if (threadIdx.x == 0) g_row[NN] = carry;
}

__global__ void k_scatter(const void* __restrict__ eiv,
                          const float* __restrict__ ea) {
    int e = blockIdx.x * blockDim.x + threadIdx.x;
    if (e >= NE) return;
    int src = load_idx(eiv, e);
    int dst = load_idx(eiv, (long long)NE + e);
    if ((unsigned)dst >= NN) return;
    if ((unsigned)src >= NN) src = 0;
    int pos = atomicAdd(&g_cur[dst], 1);
    g_psrc[pos] = src;
#pragma unroll
    for (int i = 0; i < 5; i++) g_pea[pos * 5 + i] = ea[e * 5 + i];
}

// ---------------- node projection (only for iteration 0) ----------------
__global__ void k_np(const float* __restrict__ x,
                     const float* __restrict__ w10,
                     const float* __restrict__ b10) {
    int t = blockIdx.x * blockDim.x + threadIdx.x;
    if (t >= NN * 32) return;
    int n = t >> 5, l = t & 31;
    float v0 = b10[l], v1 = b10[l + 32];
#pragma unroll
    for (int i = 0; i < 8; i++) {
        float xv = x[n * 8 + i];
        v0 = fmaf(xv, w10[i * 64 + l], v0);
        v1 = fmaf(xv, w10[i * 64 + l + 32], v1);
    }
    g_np2[t] = make_float2(v0, v1);
}

// ---------------- fused edge MLP + segment max (persistent warps) ----------------
__global__ void __launch_bounds__(256) k_edge(int it,
                                              const float* __restrict__ w10,
                                              const float* __restrict__ w11,
                                              const float* __restrict__ b11) {
    __shared__ float2 shw[64 * 32];  // w1_1 as (col l, col l+32) pairs per row k
    int tid = threadIdx.x;
    for (int i = tid; i < 64 * 32; i += 256) {
        int k = i >> 5, l = i & 31;
        shw[i] = make_float2(w11[k * 64 + l], w11[k * 64 + l + 32]);
    }
    int lane = tid & 31;
    float2 w10r[5];
#pragma unroll
    for (int i = 0; i < 5; i++)
        w10r[i] = make_float2(w10[(8 + i) * 64 + lane], w10[(8 + i) * 64 + 32 + lane]);
    float2 bb = make_float2(b11[lane], b11[lane + 32]);
    __syncthreads();

    while (true) {
        int n;
        if (lane == 0) n = atomicAdd(&g_wctr[it], 1);
        n = __shfl_sync(FULL, n, 0);
        if (n >= NN) break;

        int s = g_row[n], e = g_row[n + 1];
        float a0 = 0.f, a1 = 0.f;

        for (int eb = s; eb < e; eb += 4) {
            int idx[4];
#pragma unroll
            for (int j = 0; j < 4; j++) idx[j] = min(eb + j, e - 1);

            float hl[4], hh[4], eav[4];
#pragma unroll
            for (int j = 0; j < 4; j++) {
                int src = g_psrc[idx[j]];
                float2 np = g_np2[src * 32 + lane];
                hl[j] = np.x;
                hh[j] = np.y;
                eav[j] = (lane < 5) ? g_pea[idx[j] * 5 + lane] : 0.f;
            }
#pragma unroll
            for (int i = 0; i < 5; i++) {
#pragma unroll
                for (int j = 0; j < 4; j++) {
                    float sv = __shfl_sync(FULL, eav[j], i);
                    hl[j] = fmaf(sv, w10r[i].x, hl[j]);
                    hh[j] = fmaf(sv, w10r[i].y, hh[j]);
                }
            }
            float m0[4], m1[4];
#pragma unroll
            for (int j = 0; j < 4; j++) {
                hl[j] = fmaxf(hl[j], 0.f);
                hh[j] = fmaxf(hh[j], 0.f);
                m0[j] = bb.x;
                m1[j] = bb.y;
            }
#pragma unroll
            for (int k = 0; k < 32; k++) {
                float2 wv = shw[k * 32 + lane];
#pragma unroll
                for (int j = 0; j < 4; j++) {
                    float hk = __shfl_sync(FULL, hl[j], k);
                    m0[j] = fmaf(hk, wv.x, m0[j]);
                    m1[j] = fmaf(hk, wv.y, m1[j]);
                }
            }
#pragma unroll
            for (int k = 0; k < 32; k++) {
                float2 wv = shw[(k + 32) * 32 + lane];
#pragma unroll
                for (int j = 0; j < 4; j++) {
                    float hk = __shfl_sync(FULL, hh[j], k);
                    m0[j] = fmaf(hk, wv.x, m0[j]);
                    m1[j] = fmaf(hk, wv.y, m1[j]);
                }
            }
#pragma unroll
            for (int j = 0; j < 4; j++) {
                a0 = fmaxf(a0, fmaxf(m0[j], 0.f));
                a1 = fmaxf(a1, fmaxf(m1[j], 0.f));
            }
        }
        g_ag2[n * 32 + lane] = make_float2(a0, a1);
    }
}

// ---------------- node MLP + normalize + output + NEXT node-projection ----------------
__global__ void __launch_bounds__(256) k_node(const float* __restrict__ x_ext,
                                              float* __restrict__ out_ext, int it,
                                              const float* __restrict__ w20,
                                              const float* __restrict__ b20,
                                              const float* __restrict__ w21,
                                              const float* __restrict__ b21,
                                              const float* __restrict__ w10,
                                              const float* __restrict__ b10) {
    const float* xin = (it == 0) ? x_ext : g_xb + ((it + 1) & 1) * NN * 8;
    float* xout = (it == 7) ? out_ext : g_xb + (it & 1) * NN * 8;

    __shared__ float shw[72 * 32];
    __shared__ float shw10[8 * 64];
    int tid = threadIdx.x;
    for (int i = tid; i < 72 * 32; i += 256) shw[i] = w20[i];
    for (int i = tid; i < 8 * 64; i += 256) shw10[i] = w10[i];
    int lane = tid & 31, w = tid >> 5;
    float w21r[5];
#pragma unroll
    for (int j = 0; j < 5; j++) w21r[j] = w21[lane * 5 + j];
    __syncthreads();

    int n = blockIdx.x * 8 + w;
    float2 a2 = g_ag2[n * 32 + lane];
    float xv = (lane < 8) ? xin[n * 8 + lane] : 0.f;
    float acc = b20[lane];
#pragma unroll
    for (int i = 0; i < 8; i++) {
        float s = __shfl_sync(FULL, xv, i);
        acc = fmaf(s, shw[i * 32 + lane], acc);
    }
#pragma unroll
    for (int i = 0; i < 32; i++) {
        float s = __shfl_sync(FULL, a2.x, i);
        acc = fmaf(s, shw[(8 + i) * 32 + lane], acc);
    }
#pragma unroll
    for (int i = 0; i < 32; i++) {
        float s = __shfl_sync(FULL, a2.y, i);
        acc = fmaf(s, shw[(40 + i) * 32 + lane], acc);
    }
    acc = fmaxf(acc, 0.f);

    float p0 = acc * w21r[0], p1 = acc * w21r[1], p2 = acc * w21r[2],
          p3 = acc * w21r[3], p4 = acc * w21r[4];
#pragma unroll
    for (int off = 16; off > 0; off >>= 1) {
        p0 += __shfl_xor_sync(FULL, p0, off);
        p1 += __shfl_xor_sync(FULL, p1, off);
        p2 += __shfl_xor_sync(FULL, p2, off);
        p3 += __shfl_xor_sync(FULL, p3, off);
        p4 += __shfl_xor_sync(FULL, p4, off);
    }
    float links = p0 + b21[0];
    float c0 = p1 + b21[1], c1 = p2 + b21[2], c2 = p3 + b21[3], c3 = p4 + b21[4];
    float nor = sqrtf(c0 * c0 + c1 * c1 + c2 * c2 + c3 * c3);
    float scale = 1.f / fmaxf(1.f, nor);

    float outv = 0.f;
    if (lane == 0)      outv = links;
    else if (lane == 1) outv = c0 * scale;
    else if (lane == 2) outv = c1 * scale;
    else if (lane == 3) outv = c2 * scale;
    else if (lane == 4) outv = c3 * scale;
    else if (lane < 8)  outv = xin[n * 8 + (lane - 5)];
    if (lane < 8) xout[n * 8 + lane] = outv;

    // fused node-projection for the NEXT iteration (skipped on the last)
    if (it < 7) {
        float v0 = b10[lane], v1 = b10[lane + 32];
#pragma unroll
        for (int i = 0; i < 8; i++) {
            float s = __shfl_sync(FULL, outv, i);
            v0 = fmaf(s, shw10[i * 64 + lane], v0);
            v1 = fmaf(s, shw10[i * 64 + lane + 32], v1);
        }
        g_np2[n * 32 + lane] = make_float2(v0, v1);
    }
}

// ---------------- launch ----------------
extern "C" void kernel_launch(void* const* d_in, const int* in_sizes, int n_in,
                              void* d_out, int out_size) {
    const float* x = 0; const float* ea = 0; const void* ei = 0;
    const float* w10 = 0; const float* b10 = 0; const float* w11 = 0; const float* b11 = 0;
    const float* w20 = 0; const float* b20 = 0; const float* w21 = 0; const float* b21 = 0;
    for (int i = 0; i < n_in; i++) {
        int sz = in_sizes[i];
        const void* p = d_in[i];
        switch (sz) {
            case 400000:   x   = (const float*)p; break;
            case 16000000: ea  = (const float*)p; break;
            case 6400000:  ei  = p; break;
            case 832:      w10 = (const float*)p; break;
            case 64:       if (!b10) b10 = (const float*)p; else b11 = (const float*)p; break;
            case 4096:     w11 = (const float*)p; break;
            case 2304:     w20 = (const float*)p; break;
            case 32:       b20 = (const float*)p; break;
            case 160:      w21 = (const float*)p; break;
            case 5:        b21 = (const float*)p; break;
            case 1600000:  x   = (const float*)p; break;
            case 64000000: ea  = (const float*)p; break;
            case 51200000: ei  = p; break;
            case 25600000: ei  = p; break;
            case 3328:     w10 = (const float*)p; break;
            case 256:      if (!b10) b10 = (const float*)p; else b11 = (const float*)p; break;
            case 16384:    w11 = (const float*)p; break;
            case 9216:     w20 = (const float*)p; break;
            case 128:      b20 = (const float*)p; break;
            case 640:      w21 = (const float*)p; break;
            case 20:       b21 = (const float*)p; break;
            default: break;
        }
    }
    if (!x || !ea || !ei || !w10 || !b10 || !w11 || !b11 || !w20 || !b20 || !w21 || !b21) {
        if (n_in >= 11) {
            x   = (const float*)d_in[0];
            ea  = (const float*)d_in[1];
            ei  = d_in[2];
            w10 = (const float*)d_in[3];
            b10 = (const float*)d_in[4];
            w11 = (const float*)d_in[5];
            b11 = (const float*)d_in[6];
            w20 = (const float*)d_in[7];
            b20 = (const float*)d_in[8];
            w21 = (const float*)d_in[9];
            b21 = (const float*)d_in[10];
        }
    }
    float* out = (float*)d_out;

    // one-time (per launch) edge grouping by dst
    k_detect<<<1, 256>>>((const unsigned int*)ei);
    k_zero<<<(NN + 255) / 256, 256>>>();
    k_hist<<<(NE + 255) / 256, 256>>>(ei);
    k_scan<<<1, 1024>>>();
    k_scatter<<<(NE + 255) / 256, 256>>>(ei, ea);

    // node projection for iteration 0 only (later iters fused into k_node)
    k_np<<<(NN * 32 + 255) / 256, 256>>>(x, w10, b10);

    for (int it = 0; it < 8; it++) {
        k_edge<<<592, 256>>>(it, w10, w11, b11);
        k_node<<<NN / 8, 256>>>(x, out, it, w20, b20, w21, b21, w10, b10);
    }
}